// round 1
// baseline (speedup 1.0000x reference)
#include <cuda_runtime.h>
#include <math.h>
#include <math_constants.h>

#define BN 8192
#define DIM 256
#define NB 1024

// ------------------- scratch (device globals; no allocs allowed) -------------
static __device__ float  g_Da[(size_t)BN * BN];   // 256 MB
static __device__ float  g_Db[(size_t)BN * BN];   // 256 MB
static __device__ float  g_xx_a[BN];
static __device__ float  g_xx_b[BN];
static __device__ double g_rowsum_a[BN];
static __device__ double g_rowsum_b[BN];
static __device__ float  g_rowmean_a[BN];
static __device__ float  g_rowmean_b[BN];
static __device__ double g_grand[2];
static __device__ float  g_grandmean[2];
static __device__ double g_prod[3];               // sum(A*B), sum(A*A), sum(B*B)
// Cox buckets: task 0 = OS, task 1 = RFS
static __device__ double g_Sexp[2 * NB];
static __device__ double g_Sevexp[2 * NB];
static __device__ double g_Sevr[2 * NB];
static __device__ int    g_dcnt[2 * NB];
static __device__ float  g_maxr[2];
static __device__ double g_cox[2];

// ------------------------------- zero ---------------------------------------
__global__ void k_zero() {
    int t = blockIdx.x * blockDim.x + threadIdx.x;
    if (t < BN) { g_rowsum_a[t] = 0.0; g_rowsum_b[t] = 0.0; }
    if (t < 2 * NB) { g_Sexp[t] = 0.0; g_Sevexp[t] = 0.0; g_Sevr[t] = 0.0; g_dcnt[t] = 0; }
    if (t == 0) {
        g_grand[0] = 0.0; g_grand[1] = 0.0;
        g_prod[0] = 0.0; g_prod[1] = 0.0; g_prod[2] = 0.0;
    }
}

// ------------------------------- max risk -----------------------------------
__global__ void k_max(const float* __restrict__ r0, const float* __restrict__ r1) {
    const float* r = blockIdx.x ? r1 : r0;
    __shared__ float s[256];
    float m = -CUDART_INF_F;
    for (int i = threadIdx.x; i < BN; i += 256) m = fmaxf(m, r[i]);
    s[threadIdx.x] = m;
    __syncthreads();
    for (int o = 128; o > 0; o >>= 1) {
        if (threadIdx.x < o) s[threadIdx.x] = fmaxf(s[threadIdx.x], s[threadIdx.x + o]);
        __syncthreads();
    }
    if (threadIdx.x == 0) g_maxr[blockIdx.x] = s[0];
}

// ------------------------------- cox buckets --------------------------------
__global__ void k_bucket(const float* __restrict__ r0, const int* __restrict__ e0,
                         const int* __restrict__ t0,
                         const float* __restrict__ r1, const int* __restrict__ e1,
                         const int* __restrict__ t1) {
    int task = blockIdx.y;
    int i = blockIdx.x * 256 + threadIdx.x;
    if (i >= BN) return;
    const float* r = task ? r1 : r0;
    const int* ev = task ? e1 : e0;
    const int* tm = task ? t1 : t0;
    float mr = g_maxr[task];
    float rs = r[i] - mr;
    double er = exp((double)rs);
    int t = tm[i];
    t = t < 0 ? 0 : (t > NB - 1 ? NB - 1 : t);
    int base = task * NB;
    atomicAdd(&g_Sexp[base + t], er);
    if (ev[i]) {
        atomicAdd(&g_Sevexp[base + t], er);
        atomicAdd(&g_Sevr[base + t], (double)rs);
        atomicAdd(&g_dcnt[base + t], 1);
    }
}

// ------------------------------- cox final ----------------------------------
__global__ void k_cox() {
    int task = threadIdx.x;
    if (task >= 2) return;
    int base = task * NB;
    double cum = 0.0, num = 0.0;
    double nev = 0.0;
    for (int t = NB - 1; t >= 0; --t) {
        cum += g_Sexp[base + t];
        int d = g_dcnt[base + t];
        if (d > 0) {
            double tes = g_Sevexp[base + t];
            num += g_Sevr[base + t];
            double dd = (double)d;
            for (int l = 0; l < d; ++l)
                num -= log(cum - ((double)l / dd) * tes + 1e-12);
            nev += dd;
        }
    }
    g_cox[task] = -num / (nev + 1e-12);
}

// ------------------------------- row norms ----------------------------------
__global__ void k_xx(const float* __restrict__ za, const float* __restrict__ zb) {
    int row = blockIdx.x * 8 + (threadIdx.x >> 5);
    int lane = threadIdx.x & 31;
    if (row >= BN) return;
    const float* pa = za + (size_t)row * DIM;
    const float* pb = zb + (size_t)row * DIM;
    float sa = 0.f, sb = 0.f;
    for (int k = lane; k < DIM; k += 32) {
        float va = pa[k]; sa += va * va;
        float vb = pb[k]; sb += vb * vb;
    }
    for (int o = 16; o; o >>= 1) {
        sa += __shfl_down_sync(0xffffffffu, sa, o);
        sb += __shfl_down_sync(0xffffffffu, sb, o);
    }
    if (lane == 0) { g_xx_a[row] = sa; g_xx_b[row] = sb; }
}

// -------------------- fused gram + distance + rowsum (pass 1) ---------------
// 64x64 tile, 256 threads (16x16), each thread computes 4x4 for BOTH matrices.
__global__ void __launch_bounds__(256) k_dist(const float* __restrict__ za,
                                              const float* __restrict__ zb) {
    int bi = blockIdx.y, bj = blockIdx.x;
    if (bj < bi) return;   // symmetry: only upper triangle of tiles

    __shared__ float sAi[32][64];
    __shared__ float sAj[32][64];
    __shared__ float sBi[32][64];
    __shared__ float sBj[32][64];
    __shared__ double s_row_a[64], s_col_a[64], s_row_b[64], s_col_b[64];

    int tid = threadIdx.x;
    int tx = tid & 15, ty = tid >> 4;
    if (tid < 64) { s_row_a[tid] = 0.0; s_col_a[tid] = 0.0; s_row_b[tid] = 0.0; s_col_b[tid] = 0.0; }

    int i0 = bi * 64, j0 = bj * 64;
    float acc_a[4][4] = {};
    float acc_b[4][4] = {};

    for (int kc = 0; kc < DIM; kc += 32) {
        __syncthreads();
#pragma unroll
        for (int l = 0; l < 2; ++l) {
            int f = tid * 2 + l;         // 0..511 float4 slots
            int row = f >> 3;            // 0..63
            int k4 = (f & 7) * 4;        // 0..28
            float4 va = *(const float4*)(za + (size_t)(i0 + row) * DIM + kc + k4);
            sAi[k4 + 0][row] = va.x; sAi[k4 + 1][row] = va.y;
            sAi[k4 + 2][row] = va.z; sAi[k4 + 3][row] = va.w;
            float4 wa = *(const float4*)(za + (size_t)(j0 + row) * DIM + kc + k4);
            sAj[k4 + 0][row] = wa.x; sAj[k4 + 1][row] = wa.y;
            sAj[k4 + 2][row] = wa.z; sAj[k4 + 3][row] = wa.w;
            float4 vb = *(const float4*)(zb + (size_t)(i0 + row) * DIM + kc + k4);
            sBi[k4 + 0][row] = vb.x; sBi[k4 + 1][row] = vb.y;
            sBi[k4 + 2][row] = vb.z; sBi[k4 + 3][row] = vb.w;
            float4 wb = *(const float4*)(zb + (size_t)(j0 + row) * DIM + kc + k4);
            sBj[k4 + 0][row] = wb.x; sBj[k4 + 1][row] = wb.y;
            sBj[k4 + 2][row] = wb.z; sBj[k4 + 3][row] = wb.w;
        }
        __syncthreads();
#pragma unroll
        for (int k = 0; k < 32; ++k) {
            float4 ai = *(const float4*)&sAi[k][ty * 4];
            float4 aj = *(const float4*)&sAj[k][tx * 4];
            float4 bi4 = *(const float4*)&sBi[k][ty * 4];
            float4 bj4 = *(const float4*)&sBj[k][tx * 4];
            float am[4] = {ai.x, ai.y, ai.z, ai.w};
            float an[4] = {aj.x, aj.y, aj.z, aj.w};
            float bm[4] = {bi4.x, bi4.y, bi4.z, bi4.w};
            float bn[4] = {bj4.x, bj4.y, bj4.z, bj4.w};
#pragma unroll
            for (int m = 0; m < 4; ++m)
#pragma unroll
                for (int n = 0; n < 4; ++n) {
                    acc_a[m][n] = fmaf(am[m], an[n], acc_a[m][n]);
                    acc_b[m][n] = fmaf(bm[m], bn[n], acc_b[m][n]);
                }
        }
    }

    // epilogue: distances, scratch write, rowsum accumulation
    float xa_i[4], xa_j[4], xb_i[4], xb_j[4];
#pragma unroll
    for (int m = 0; m < 4; ++m) { xa_i[m] = g_xx_a[i0 + ty * 4 + m]; xb_i[m] = g_xx_b[i0 + ty * 4 + m]; }
#pragma unroll
    for (int n = 0; n < 4; ++n) { xa_j[n] = g_xx_a[j0 + tx * 4 + n]; xb_j[n] = g_xx_b[j0 + tx * 4 + n]; }

    double ra[4] = {0, 0, 0, 0}, ca[4] = {0, 0, 0, 0};
    double rb[4] = {0, 0, 0, 0}, cb[4] = {0, 0, 0, 0};
    bool off = (bi != bj);
#pragma unroll
    for (int m = 0; m < 4; ++m) {
        size_t gi = (size_t)(i0 + ty * 4 + m);
#pragma unroll
        for (int n = 0; n < 4; ++n) {
            size_t gj = (size_t)(j0 + tx * 4 + n);
            float d2a = xa_i[m] + xa_j[n] - 2.0f * acc_a[m][n];
            float Da = sqrtf(fmaxf(d2a, 1e-8f));
            float d2b = xb_i[m] + xb_j[n] - 2.0f * acc_b[m][n];
            float Db = sqrtf(fmaxf(d2b, 1e-8f));
            g_Da[gi * BN + gj] = Da;
            g_Db[gi * BN + gj] = Db;
            if (off) { g_Da[gj * BN + gi] = Da; g_Db[gj * BN + gi] = Db; }
            ra[m] += (double)Da; ca[n] += (double)Da;
            rb[m] += (double)Db; cb[n] += (double)Db;
        }
    }
#pragma unroll
    for (int m = 0; m < 4; ++m) {
        atomicAdd(&s_row_a[ty * 4 + m], ra[m]);
        atomicAdd(&s_row_b[ty * 4 + m], rb[m]);
    }
    if (off) {
#pragma unroll
        for (int n = 0; n < 4; ++n) {
            atomicAdd(&s_col_a[tx * 4 + n], ca[n]);
            atomicAdd(&s_col_b[tx * 4 + n], cb[n]);
        }
    }
    __syncthreads();
    if (tid < 64) {
        atomicAdd(&g_rowsum_a[i0 + tid], s_row_a[tid]);
        atomicAdd(&g_rowsum_b[i0 + tid], s_row_b[tid]);
        if (off) {
            atomicAdd(&g_rowsum_a[j0 + tid], s_col_a[tid]);
            atomicAdd(&g_rowsum_b[j0 + tid], s_col_b[tid]);
        }
    }
    if (tid == 0) {
        double ta = 0.0, tb = 0.0;
        for (int t = 0; t < 64; ++t) { ta += s_row_a[t]; tb += s_row_b[t]; }
        double w = off ? 2.0 : 1.0;
        atomicAdd(&g_grand[0], w * ta);
        atomicAdd(&g_grand[1], w * tb);
    }
}

// ------------------------------- means --------------------------------------
__global__ void k_means() {
    int t = blockIdx.x * blockDim.x + threadIdx.x;
    if (t < BN) {
        g_rowmean_a[t] = (float)(g_rowsum_a[t] / (double)BN);
        g_rowmean_b[t] = (float)(g_rowsum_b[t] / (double)BN);
    }
    if (t == 0) {
        double Nd = (double)BN * (double)BN;
        g_grandmean[0] = (float)(g_grand[0] / Nd);
        g_grandmean[1] = (float)(g_grand[1] / Nd);
    }
}

// ---------------------- centering + products (pass 2) -----------------------
__global__ void __launch_bounds__(256) k_center() {
    int i = blockIdx.x;
    float ma = g_rowmean_a[i], mb = g_rowmean_b[i];
    float ga = g_grandmean[0], gb = g_grandmean[1];
    const float4* Da = (const float4*)(g_Da + (size_t)i * BN);
    const float4* Db = (const float4*)(g_Db + (size_t)i * BN);
    const float4* qa = (const float4*)g_rowmean_a;
    const float4* qb = (const float4*)g_rowmean_b;
    double sAB = 0.0, sAA = 0.0, sBB = 0.0;
    for (int j = threadIdx.x; j < BN / 4; j += 256) {
        float4 da = Da[j], db = Db[j], ra = qa[j], rb = qb[j];
        {
            float A = da.x - ma - ra.x + ga, Bv = db.x - mb - rb.x + gb;
            sAB += (double)A * (double)Bv; sAA += (double)A * (double)A; sBB += (double)Bv * (double)Bv;
        }
        {
            float A = da.y - ma - ra.y + ga, Bv = db.y - mb - rb.y + gb;
            sAB += (double)A * (double)Bv; sAA += (double)A * (double)A; sBB += (double)Bv * (double)Bv;
        }
        {
            float A = da.z - ma - ra.z + ga, Bv = db.z - mb - rb.z + gb;
            sAB += (double)A * (double)Bv; sAA += (double)A * (double)A; sBB += (double)Bv * (double)Bv;
        }
        {
            float A = da.w - ma - ra.w + ga, Bv = db.w - mb - rb.w + gb;
            sAB += (double)A * (double)Bv; sAA += (double)A * (double)A; sBB += (double)Bv * (double)Bv;
        }
    }
    __shared__ double s0[256], s1[256], s2[256];
    s0[threadIdx.x] = sAB; s1[threadIdx.x] = sAA; s2[threadIdx.x] = sBB;
    __syncthreads();
    for (int o = 128; o > 0; o >>= 1) {
        if (threadIdx.x < o) {
            s0[threadIdx.x] += s0[threadIdx.x + o];
            s1[threadIdx.x] += s1[threadIdx.x + o];
            s2[threadIdx.x] += s2[threadIdx.x + o];
        }
        __syncthreads();
    }
    if (threadIdx.x == 0) {
        atomicAdd(&g_prod[0], s0[0]);
        atomicAdd(&g_prod[1], s1[0]);
        atomicAdd(&g_prod[2], s2[0]);
    }
}

// ------------------------------- final --------------------------------------
__global__ void k_final(const float* __restrict__ intra_wsi,
                        const float* __restrict__ intra_ct,
                        float* __restrict__ out) {
    double Nd = (double)BN * (double)BN;
    double dcov = g_prod[0] / Nd;
    double va = g_prod[1] / Nd;
    double vb = g_prod[2] / Nd;
    double l_cca = 1.0 - dcov / sqrt(fmax(va * vb, 1e-8));
    double l_intra = (double)intra_wsi[0] + (double)intra_ct[0];
    // OS_W=1, RFS_W=1, AUX_W=1, CCA_W=0.1, INTRA_W=0.05
    double total = g_cox[0] + g_cox[1] + (0.1 * l_cca + 0.05 * l_intra);
    out[0] = (float)total;
}

// ------------------------------- launch -------------------------------------
extern "C" void kernel_launch(void* const* d_in, const int* in_sizes, int n_in,
                              void* d_out, int out_size) {
    const float* risk_os  = (const float*)d_in[0];
    const float* risk_rfs = (const float*)d_in[1];
    const float* z_ct     = (const float*)d_in[2];
    const float* z_wsi    = (const float*)d_in[3];
    const float* intra_wsi = (const float*)d_in[4];
    const float* intra_ct  = (const float*)d_in[5];
    const int* evt_os  = (const int*)d_in[6];
    const int* tm_os   = (const int*)d_in[7];
    const int* evt_rfs = (const int*)d_in[8];
    const int* tm_rfs  = (const int*)d_in[9];
    float* out = (float*)d_out;

    k_zero<<<(BN + 255) / 256, 256>>>();
    k_max<<<2, 256>>>(risk_os, risk_rfs);
    k_bucket<<<dim3(BN / 256, 2), 256>>>(risk_os, evt_os, tm_os, risk_rfs, evt_rfs, tm_rfs);
    k_cox<<<1, 32>>>();
    k_xx<<<BN / 8, 256>>>(z_ct, z_wsi);
    k_dist<<<dim3(BN / 64, BN / 64), 256>>>(z_ct, z_wsi);
    k_means<<<(BN + 255) / 256, 256>>>();
    k_center<<<BN, 256>>>();
    k_final<<<1, 1>>>(intra_wsi, intra_ct, out);
}

// round 3
// speedup vs baseline: 1.7435x; 1.7435x over previous
#include <cuda_runtime.h>
#include <cuda_bf16.h>
#include <cstdint>
#include <math.h>
#include <math_constants.h>

#define BN 8192
#define DIM 256
#define NB 1024
#define TS 128
#define KC 32
#define KST 40   // padded bf16 stride (conflict-free: 20 words/row)

// ------------------- scratch (device globals; no allocs allowed) -------------
static __device__ __nv_bfloat16 g_za16[(size_t)BN * DIM];
static __device__ __nv_bfloat16 g_zb16[(size_t)BN * DIM];
static __device__ float  g_xx_a[BN];
static __device__ float  g_xx_b[BN];
static __device__ double g_rowsum_a[BN];
static __device__ double g_rowsum_b[BN];
static __device__ double g_grand[2];    // sum Da, sum Db (full matrix)
static __device__ double g_prod[3];     // sum DaDb, sum Da^2, sum Db^2
// Cox buckets: task 0 = OS, task 1 = RFS
static __device__ double g_Sexp[2 * NB];
static __device__ double g_Sevexp[2 * NB];
static __device__ double g_Sevr[2 * NB];
static __device__ int    g_dcnt[2 * NB];
static __device__ float  g_maxr[2];
static __device__ double g_cox[2];

// ------------------------------- zero ---------------------------------------
__global__ void k_zero() {
    int t = blockIdx.x * blockDim.x + threadIdx.x;
    if (t < BN) { g_rowsum_a[t] = 0.0; g_rowsum_b[t] = 0.0; }
    if (t < 2 * NB) { g_Sexp[t] = 0.0; g_Sevexp[t] = 0.0; g_Sevr[t] = 0.0; g_dcnt[t] = 0; }
    if (t == 0) {
        g_grand[0] = 0.0; g_grand[1] = 0.0;
        g_prod[0] = 0.0; g_prod[1] = 0.0; g_prod[2] = 0.0;
    }
}

// ------------------------------- max risk -----------------------------------
__global__ void k_max(const float* __restrict__ r0, const float* __restrict__ r1) {
    const float* r = blockIdx.x ? r1 : r0;
    __shared__ float s[256];
    float m = -CUDART_INF_F;
    for (int i = threadIdx.x; i < BN; i += 256) m = fmaxf(m, r[i]);
    s[threadIdx.x] = m;
    __syncthreads();
    for (int o = 128; o > 0; o >>= 1) {
        if (threadIdx.x < o) s[threadIdx.x] = fmaxf(s[threadIdx.x], s[threadIdx.x + o]);
        __syncthreads();
    }
    if (threadIdx.x == 0) g_maxr[blockIdx.x] = s[0];
}

// ------------------------------- cox buckets --------------------------------
__global__ void k_bucket(const float* __restrict__ r0, const int* __restrict__ e0,
                         const int* __restrict__ t0,
                         const float* __restrict__ r1, const int* __restrict__ e1,
                         const int* __restrict__ t1) {
    int task = blockIdx.y;
    int i = blockIdx.x * 256 + threadIdx.x;
    if (i >= BN) return;
    const float* r = task ? r1 : r0;
    const int* ev = task ? e1 : e0;
    const int* tm = task ? t1 : t0;
    float mr = g_maxr[task];
    float rs = r[i] - mr;
    double er = exp((double)rs);
    int t = tm[i];
    t = t < 0 ? 0 : (t > NB - 1 ? NB - 1 : t);
    int base = task * NB;
    atomicAdd(&g_Sexp[base + t], er);
    if (ev[i]) {
        atomicAdd(&g_Sevexp[base + t], er);
        atomicAdd(&g_Sevr[base + t], (double)rs);
        atomicAdd(&g_dcnt[base + t], 1);
    }
}

// ------------------------------- cox final ----------------------------------
__global__ void k_cox() {
    int task = threadIdx.x;
    if (task >= 2) return;
    int base = task * NB;
    double cum = 0.0, num = 0.0;
    double nev = 0.0;
    for (int t = NB - 1; t >= 0; --t) {
        cum += g_Sexp[base + t];
        int d = g_dcnt[base + t];
        if (d > 0) {
            double tes = g_Sevexp[base + t];
            num += g_Sevr[base + t];
            double dd = (double)d;
            for (int l = 0; l < d; ++l)
                num -= log(cum - ((double)l / dd) * tes + 1e-12);
            nev += dd;
        }
    }
    g_cox[task] = -num / (nev + 1e-12);
}

// --------------------- convert to bf16 + row norms ---------------------------
__global__ void k_cvt(const float* __restrict__ za, const float* __restrict__ zb) {
    int row = blockIdx.x * 8 + (threadIdx.x >> 5);
    int lane = threadIdx.x & 31;
    if (row >= BN) return;
    const float* pa = za + (size_t)row * DIM;
    const float* pb = zb + (size_t)row * DIM;
    float sa = 0.f, sb = 0.f;
    for (int k = lane; k < DIM; k += 32) {
        __nv_bfloat16 ha = __float2bfloat16(pa[k]);
        __nv_bfloat16 hb = __float2bfloat16(pb[k]);
        g_za16[(size_t)row * DIM + k] = ha;
        g_zb16[(size_t)row * DIM + k] = hb;
        float fa = __bfloat162float(ha); sa += fa * fa;
        float fb = __bfloat162float(hb); sb += fb * fb;
    }
    for (int o = 16; o; o >>= 1) {
        sa += __shfl_down_sync(0xffffffffu, sa, o);
        sb += __shfl_down_sync(0xffffffffu, sb, o);
    }
    if (lane == 0) { g_xx_a[row] = sa; g_xx_b[row] = sb; }
}

// ------------------------------- mma helper ----------------------------------
__device__ __forceinline__ void mma16816(float* c, const uint32_t* a, const uint32_t* b) {
    asm volatile(
        "mma.sync.aligned.m16n8k16.row.col.f32.bf16.bf16.f32 "
        "{%0,%1,%2,%3},{%4,%5,%6,%7},{%8,%9},{%0,%1,%2,%3};"
        : "+f"(c[0]), "+f"(c[1]), "+f"(c[2]), "+f"(c[3])
        : "r"(a[0]), "r"(a[1]), "r"(a[2]), "r"(a[3]), "r"(b[0]), "r"(b[1]));
}

// ------------- fused dual-gram + distance + all reductions (one pass) --------
// 128x128 tile, 8 warps; warp = 64x32 via 4x4 m16n8k16 fragments, both matrices.
__global__ void __launch_bounds__(256) k_dist() {
    int bi = blockIdx.y, bj = blockIdx.x;
    if (bj < bi) return;   // symmetry: only upper triangle of tiles

    __shared__ __nv_bfloat16 sAi[TS][KST];
    __shared__ __nv_bfloat16 sAj[TS][KST];
    __shared__ __nv_bfloat16 sBi[TS][KST];
    __shared__ __nv_bfloat16 sBj[TS][KST];

    int tid = threadIdx.x;
    int lane = tid & 31, warp = tid >> 5;
    int g = lane >> 2, t = lane & 3;
    int m_off = (warp >> 2) * 64;      // 0 or 64
    int n_off = (warp & 3) * 32;       // 0,32,64,96
    int i0 = bi * TS, j0 = bj * TS;

    float accA[4][4][4];
    float accB[4][4][4];
#pragma unroll
    for (int mi = 0; mi < 4; ++mi)
#pragma unroll
        for (int ni = 0; ni < 4; ++ni)
#pragma unroll
            for (int cc = 0; cc < 4; ++cc) { accA[mi][ni][cc] = 0.f; accB[mi][ni][cc] = 0.f; }

    for (int kc = 0; kc < DIM; kc += KC) {
        __syncthreads();
#pragma unroll
        for (int l = 0; l < 2; ++l) {
            int f = tid + l * 256;          // 0..511
            int row = f >> 2;               // 0..127
            int c8 = (f & 3) * 8;           // 0,8,16,24
            *(uint4*)&sAi[row][c8] = *(const uint4*)(g_za16 + (size_t)(i0 + row) * DIM + kc + c8);
            *(uint4*)&sAj[row][c8] = *(const uint4*)(g_za16 + (size_t)(j0 + row) * DIM + kc + c8);
            *(uint4*)&sBi[row][c8] = *(const uint4*)(g_zb16 + (size_t)(i0 + row) * DIM + kc + c8);
            *(uint4*)&sBj[row][c8] = *(const uint4*)(g_zb16 + (size_t)(j0 + row) * DIM + kc + c8);
        }
        __syncthreads();
#pragma unroll
        for (int ks = 0; ks < KC; ks += 16) {
            // ---- matrix A ----
            {
                uint32_t a[4][4], b[4][2];
#pragma unroll
                for (int mi = 0; mi < 4; ++mi) {
                    int r = m_off + 16 * mi + g;
                    a[mi][0] = *(const uint32_t*)&sAi[r][ks + 2 * t];
                    a[mi][1] = *(const uint32_t*)&sAi[r + 8][ks + 2 * t];
                    a[mi][2] = *(const uint32_t*)&sAi[r][ks + 2 * t + 8];
                    a[mi][3] = *(const uint32_t*)&sAi[r + 8][ks + 2 * t + 8];
                }
#pragma unroll
                for (int ni = 0; ni < 4; ++ni) {
                    int c = n_off + 8 * ni + g;
                    b[ni][0] = *(const uint32_t*)&sAj[c][ks + 2 * t];
                    b[ni][1] = *(const uint32_t*)&sAj[c][ks + 2 * t + 8];
                }
#pragma unroll
                for (int mi = 0; mi < 4; ++mi)
#pragma unroll
                    for (int ni = 0; ni < 4; ++ni)
                        mma16816(accA[mi][ni], a[mi], b[ni]);
            }
            // ---- matrix B ----
            {
                uint32_t a[4][4], b[4][2];
#pragma unroll
                for (int mi = 0; mi < 4; ++mi) {
                    int r = m_off + 16 * mi + g;
                    a[mi][0] = *(const uint32_t*)&sBi[r][ks + 2 * t];
                    a[mi][1] = *(const uint32_t*)&sBi[r + 8][ks + 2 * t];
                    a[mi][2] = *(const uint32_t*)&sBi[r][ks + 2 * t + 8];
                    a[mi][3] = *(const uint32_t*)&sBi[r + 8][ks + 2 * t + 8];
                }
#pragma unroll
                for (int ni = 0; ni < 4; ++ni) {
                    int c = n_off + 8 * ni + g;
                    b[ni][0] = *(const uint32_t*)&sBj[c][ks + 2 * t];
                    b[ni][1] = *(const uint32_t*)&sBj[c][ks + 2 * t + 8];
                }
#pragma unroll
                for (int mi = 0; mi < 4; ++mi)
#pragma unroll
                    for (int ni = 0; ni < 4; ++ni)
                        mma16816(accB[mi][ni], a[mi], b[ni]);
            }
        }
    }

    // ---------------- epilogue: distances + reductions -----------------------
    float xai[8], xaj[8], xbi[8], xbj[8];
#pragma unroll
    for (int mi = 0; mi < 4; ++mi) {
        xai[2 * mi]     = g_xx_a[i0 + m_off + 16 * mi + g];
        xai[2 * mi + 1] = g_xx_a[i0 + m_off + 16 * mi + 8 + g];
        xbi[2 * mi]     = g_xx_b[i0 + m_off + 16 * mi + g];
        xbi[2 * mi + 1] = g_xx_b[i0 + m_off + 16 * mi + 8 + g];
    }
#pragma unroll
    for (int ni = 0; ni < 4; ++ni) {
        xaj[2 * ni]     = g_xx_a[j0 + n_off + 8 * ni + 2 * t];
        xaj[2 * ni + 1] = g_xx_a[j0 + n_off + 8 * ni + 2 * t + 1];
        xbj[2 * ni]     = g_xx_b[j0 + n_off + 8 * ni + 2 * t];
        xbj[2 * ni + 1] = g_xx_b[j0 + n_off + 8 * ni + 2 * t + 1];
    }

    float rsa[8], rsb[8], csa[8], csb[8];
#pragma unroll
    for (int q = 0; q < 8; ++q) { rsa[q] = 0.f; rsb[q] = 0.f; csa[q] = 0.f; csb[q] = 0.f; }
    float pAB = 0.f, pAA = 0.f, pBB = 0.f, pA = 0.f, pB = 0.f;

#pragma unroll
    for (int mi = 0; mi < 4; ++mi)
#pragma unroll
        for (int ni = 0; ni < 4; ++ni)
#pragma unroll
            for (int cc = 0; cc < 4; ++cc) {
                int rr = cc >> 1, jc = cc & 1;
                float Da = sqrtf(fmaxf(xai[2 * mi + rr] + xaj[2 * ni + jc] - 2.f * accA[mi][ni][cc], 1e-8f));
                float Db = sqrtf(fmaxf(xbi[2 * mi + rr] + xbj[2 * ni + jc] - 2.f * accB[mi][ni][cc], 1e-8f));
                rsa[2 * mi + rr] += Da; csa[2 * ni + jc] += Da;
                rsb[2 * mi + rr] += Db; csb[2 * ni + jc] += Db;
                pAB += Da * Db; pAA += Da * Da; pBB += Db * Db;
                pA += Da; pB += Db;
            }

    bool diag = (bi == bj);

    // row sums: reduce over t (quad lanes share rows)
#pragma unroll
    for (int q = 0; q < 8; ++q) {
        rsa[q] += __shfl_xor_sync(0xffffffffu, rsa[q], 1);
        rsa[q] += __shfl_xor_sync(0xffffffffu, rsa[q], 2);
        rsb[q] += __shfl_xor_sync(0xffffffffu, rsb[q], 1);
        rsb[q] += __shfl_xor_sync(0xffffffffu, rsb[q], 2);
    }
    if (t == 0) {
#pragma unroll
        for (int mi = 0; mi < 4; ++mi)
#pragma unroll
            for (int rr = 0; rr < 2; ++rr) {
                int row = i0 + m_off + 16 * mi + 8 * rr + g;
                atomicAdd(&g_rowsum_a[row], (double)rsa[2 * mi + rr]);
                atomicAdd(&g_rowsum_b[row], (double)rsb[2 * mi + rr]);
            }
    }
    // col sums (mirror contribution) only for off-diagonal tiles
    if (!diag) {
#pragma unroll
        for (int q = 0; q < 8; ++q) {
            csa[q] += __shfl_xor_sync(0xffffffffu, csa[q], 4);
            csa[q] += __shfl_xor_sync(0xffffffffu, csa[q], 8);
            csa[q] += __shfl_xor_sync(0xffffffffu, csa[q], 16);
            csb[q] += __shfl_xor_sync(0xffffffffu, csb[q], 4);
            csb[q] += __shfl_xor_sync(0xffffffffu, csb[q], 8);
            csb[q] += __shfl_xor_sync(0xffffffffu, csb[q], 16);
        }
        if (g == 0) {
#pragma unroll
            for (int ni = 0; ni < 4; ++ni)
#pragma unroll
                for (int jc = 0; jc < 2; ++jc) {
                    int col = j0 + n_off + 8 * ni + 2 * t + jc;
                    atomicAdd(&g_rowsum_a[col], (double)csa[2 * ni + jc]);
                    atomicAdd(&g_rowsum_b[col], (double)csb[2 * ni + jc]);
                }
        }
    }
    // grand + product sums (weight 2 for off-diagonal tiles)
    float w = diag ? 1.f : 2.f;
#pragma unroll
    for (int o = 16; o; o >>= 1) {
        pAB += __shfl_xor_sync(0xffffffffu, pAB, o);
        pAA += __shfl_xor_sync(0xffffffffu, pAA, o);
        pBB += __shfl_xor_sync(0xffffffffu, pBB, o);
        pA  += __shfl_xor_sync(0xffffffffu, pA, o);
        pB  += __shfl_xor_sync(0xffffffffu, pB, o);
    }
    if (lane == 0) {
        atomicAdd(&g_prod[0], (double)(w * pAB));
        atomicAdd(&g_prod[1], (double)(w * pAA));
        atomicAdd(&g_prod[2], (double)(w * pBB));
        atomicAdd(&g_grand[0], (double)(w * pA));
        atomicAdd(&g_grand[1], (double)(w * pB));
    }
}

// ------------------------------- final --------------------------------------
__global__ void k_final(const float* __restrict__ intra_wsi,
                        const float* __restrict__ intra_ct,
                        float* __restrict__ out) {
    __shared__ double s0[256], s1[256], s2[256];
    double mab = 0.0, maa = 0.0, mbb = 0.0;
    for (int i = threadIdx.x; i < BN; i += 256) {
        double ra = g_rowsum_a[i], rb = g_rowsum_b[i];
        mab += ra * rb; maa += ra * ra; mbb += rb * rb;
    }
    s0[threadIdx.x] = mab; s1[threadIdx.x] = maa; s2[threadIdx.x] = mbb;
    __syncthreads();
    for (int o = 128; o > 0; o >>= 1) {
        if (threadIdx.x < o) {
            s0[threadIdx.x] += s0[threadIdx.x + o];
            s1[threadIdx.x] += s1[threadIdx.x + o];
            s2[threadIdx.x] += s2[threadIdx.x + o];
        }
        __syncthreads();
    }
    if (threadIdx.x == 0) {
        double n = (double)BN, n2 = n * n;
        double Ga = g_grand[0], Gb = g_grand[1];
        double SAB = g_prod[0] - (2.0 / n) * s0[0] + Ga * Gb / n2;
        double SAA = g_prod[1] - (2.0 / n) * s1[0] + Ga * Ga / n2;
        double SBB = g_prod[2] - (2.0 / n) * s2[0] + Gb * Gb / n2;
        double dcov = SAB / n2;
        double va = SAA / n2;
        double vb = SBB / n2;
        double l_cca = 1.0 - dcov / sqrt(fmax(va * vb, 1e-8));
        double l_intra = (double)intra_wsi[0] + (double)intra_ct[0];
        out[0] = (float)(g_cox[0] + g_cox[1] + 0.1 * l_cca + 0.05 * l_intra);
    }
}

// ------------------------------- launch -------------------------------------
extern "C" void kernel_launch(void* const* d_in, const int* in_sizes, int n_in,
                              void* d_out, int out_size) {
    const float* risk_os  = (const float*)d_in[0];
    const float* risk_rfs = (const float*)d_in[1];
    const float* z_ct     = (const float*)d_in[2];
    const float* z_wsi    = (const float*)d_in[3];
    const float* intra_wsi = (const float*)d_in[4];
    const float* intra_ct  = (const float*)d_in[5];
    const int* evt_os  = (const int*)d_in[6];
    const int* tm_os   = (const int*)d_in[7];
    const int* evt_rfs = (const int*)d_in[8];
    const int* tm_rfs  = (const int*)d_in[9];
    float* out = (float*)d_out;

    k_zero<<<32, 256>>>();
    k_max<<<2, 256>>>(risk_os, risk_rfs);
    k_bucket<<<dim3(32, 2), 256>>>(risk_os, evt_os, tm_os, risk_rfs, evt_rfs, tm_rfs);
    k_cox<<<1, 32>>>();
    k_cvt<<<BN / 8, 256>>>(z_ct, z_wsi);
    k_dist<<<dim3(BN / TS, BN / TS), 256>>>();
    k_final<<<1, 256>>>(intra_wsi, intra_ct, out);
}

// round 5
// speedup vs baseline: 1.8191x; 1.0434x over previous
#include <cuda_runtime.h>
#include <cuda_bf16.h>
#include <cstdint>
#include <math.h>
#include <math_constants.h>

#define BN 8192
#define DIM 256
#define NB 1024
#define TS 128
#define NCHUNK 8            // K chunks of 32

// smem: xx arrays [0,2048), then 2 stages x 4 tiles x (128 rows x 80B)
#define TILE_B   10240      // 128 * 80
#define STAGE_B  40960      // 4 tiles
#define OFF_STG  2048
#define SMEM_TOTAL (OFF_STG + 2 * STAGE_B)

static __device__ __nv_bfloat16 g_za16[(size_t)BN * DIM];
static __device__ __nv_bfloat16 g_zb16[(size_t)BN * DIM];
static __device__ float  g_xx_a[BN];
static __device__ float  g_xx_b[BN];
static __device__ double g_rowsum_a[BN];
static __device__ double g_rowsum_b[BN];
static __device__ double g_grand[2];
static __device__ double g_prod[3];
static __device__ double g_Sexp[2 * NB];
static __device__ double g_Sevexp[2 * NB];
static __device__ double g_Sevr[2 * NB];
static __device__ int    g_dcnt[2 * NB];
static __device__ float  g_maxr[2];
static __device__ double g_cox[2];

// ----------------------------- helpers ---------------------------------------
__device__ __forceinline__ uint32_t smem_u32(const void* p) {
    uint32_t a;
    asm("{ .reg .u64 t; cvta.to.shared.u64 t, %1; cvt.u32.u64 %0, t; }" : "=r"(a) : "l"(p));
    return a;
}
#define CP16(d, s) asm volatile("cp.async.cg.shared.global [%0], [%1], 16;" :: "r"(d), "l"(s))
#define CP_COMMIT() asm volatile("cp.async.commit_group;" ::: "memory")
#define CP_WAIT(n)  asm volatile("cp.async.wait_group %0;" :: "n"(n) : "memory")

__device__ __forceinline__ void ldmx4(uint32_t* r, uint32_t addr) {
    asm volatile("ldmatrix.sync.aligned.m8n8.x4.shared.b16 {%0,%1,%2,%3}, [%4];"
        : "=r"(r[0]), "=r"(r[1]), "=r"(r[2]), "=r"(r[3]) : "r"(addr));
}
__device__ __forceinline__ void mma16816(float* c, const uint32_t* a, const uint32_t* b) {
    asm volatile(
        "mma.sync.aligned.m16n8k16.row.col.f32.bf16.bf16.f32 "
        "{%0,%1,%2,%3},{%4,%5,%6,%7},{%8,%9},{%0,%1,%2,%3};"
        : "+f"(c[0]), "+f"(c[1]), "+f"(c[2]), "+f"(c[3])
        : "r"(a[0]), "r"(a[1]), "r"(a[2]), "r"(a[3]), "r"(b[0]), "r"(b[1]));
}

// ------------------------------- small kernels -------------------------------
__global__ void k_zero() {
    int t = blockIdx.x * blockDim.x + threadIdx.x;
    if (t < BN) { g_rowsum_a[t] = 0.0; g_rowsum_b[t] = 0.0; }
    if (t < 2 * NB) { g_Sexp[t] = 0.0; g_Sevexp[t] = 0.0; g_Sevr[t] = 0.0; g_dcnt[t] = 0; }
    if (t == 0) {
        g_grand[0] = g_grand[1] = 0.0;
        g_prod[0] = g_prod[1] = g_prod[2] = 0.0;
    }
}

__global__ void k_max(const float* __restrict__ r0, const float* __restrict__ r1) {
    const float* r = blockIdx.x ? r1 : r0;
    __shared__ float s[256];
    float m = -CUDART_INF_F;
    for (int i = threadIdx.x; i < BN; i += 256) m = fmaxf(m, r[i]);
    s[threadIdx.x] = m;
    __syncthreads();
    for (int o = 128; o > 0; o >>= 1) {
        if (threadIdx.x < o) s[threadIdx.x] = fmaxf(s[threadIdx.x], s[threadIdx.x + o]);
        __syncthreads();
    }
    if (threadIdx.x == 0) g_maxr[blockIdx.x] = s[0];
}

__global__ void k_bucket(const float* __restrict__ r0, const int* __restrict__ e0,
                         const int* __restrict__ t0,
                         const float* __restrict__ r1, const int* __restrict__ e1,
                         const int* __restrict__ t1) {
    int task = blockIdx.y;
    int i = blockIdx.x * 256 + threadIdx.x;
    if (i >= BN) return;
    const float* r = task ? r1 : r0;
    const int* ev = task ? e1 : e0;
    const int* tm = task ? t1 : t0;
    float rs = r[i] - g_maxr[task];
    double er = exp((double)rs);
    int t = tm[i];
    t = t < 0 ? 0 : (t > NB - 1 ? NB - 1 : t);
    int base = task * NB;
    atomicAdd(&g_Sexp[base + t], er);
    if (ev[i]) {
        atomicAdd(&g_Sevexp[base + t], er);
        atomicAdd(&g_Sevr[base + t], (double)rs);
        atomicAdd(&g_dcnt[base + t], 1);
    }
}

__global__ void k_cox() {
    int task = threadIdx.x;
    if (task >= 2) return;
    int base = task * NB;
    double cum = 0.0, num = 0.0, nev = 0.0;
    for (int t = NB - 1; t >= 0; --t) {
        cum += g_Sexp[base + t];
        int d = g_dcnt[base + t];
        if (d > 0) {
            double tes = g_Sevexp[base + t];
            num += g_Sevr[base + t];
            double dd = (double)d;
            for (int l = 0; l < d; ++l)
                num -= log(cum - ((double)l / dd) * tes + 1e-12);
            nev += dd;
        }
    }
    g_cox[task] = -num / (nev + 1e-12);
}

__global__ void k_cvt(const float* __restrict__ za, const float* __restrict__ zb) {
    int row = blockIdx.x * 8 + (threadIdx.x >> 5);
    int lane = threadIdx.x & 31;
    if (row >= BN) return;
    const float* pa = za + (size_t)row * DIM;
    const float* pb = zb + (size_t)row * DIM;
    float sa = 0.f, sb = 0.f;
    for (int k = lane; k < DIM; k += 32) {
        __nv_bfloat16 ha = __float2bfloat16(pa[k]);
        __nv_bfloat16 hb = __float2bfloat16(pb[k]);
        g_za16[(size_t)row * DIM + k] = ha;
        g_zb16[(size_t)row * DIM + k] = hb;
        float fa = __bfloat162float(ha); sa += fa * fa;
        float fb = __bfloat162float(hb); sb += fb * fb;
    }
    for (int o = 16; o; o >>= 1) {
        sa += __shfl_down_sync(0xffffffffu, sa, o);
        sb += __shfl_down_sync(0xffffffffu, sb, o);
    }
    if (lane == 0) { g_xx_a[row] = sa; g_xx_b[row] = sb; }
}

// --------- fused dual-gram distance kernel: mma.sync + ldmatrix + cp.async ---
__global__ void __launch_bounds__(512, 1) k_dist() {
    int bi = blockIdx.y, bj = blockIdx.x;
    if (bj < bi) return;
    extern __shared__ char smem[];
    uint32_t sb = smem_u32(smem);

    int tid = threadIdx.x;
    int lane = tid & 31, warp = tid >> 5;
    int wr = warp & 3, wc = warp >> 2;     // 4x4 warp grid, 32x32 warp tile
    int g = lane >> 2, t = lane & 3;
    int i0 = bi * TS, j0 = bj * TS;
    bool diag = (bi == bj);

    float* sxai = (float*)(smem);
    float* sxaj = (float*)(smem + 512);
    float* sxbi = (float*)(smem + 1024);
    float* sxbj = (float*)(smem + 1536);
    if (tid < 128) {
        sxai[tid] = g_xx_a[i0 + tid];
        sxaj[tid] = g_xx_a[j0 + tid];
        sxbi[tid] = g_xx_b[i0 + tid];
        sxbj[tid] = g_xx_b[j0 + tid];
    }

    // copy indexing (one 16B chunk per thread per tile)
    int crow = tid >> 2, cch = tid & 3;
    const char* pza = (const char*)g_za16;
    const char* pzb = (const char*)g_zb16;

    // fragment lane offsets (bytes within a tile)
    uint32_t aoff = (uint32_t)((wr * 32 + ((lane >> 3) & 1) * 8 + (lane & 7)) * 80 + (lane >> 4) * 16);
    uint32_t boff = (uint32_t)((wc * 32 + (lane >> 4) * 8 + (lane & 7)) * 80 + ((lane >> 3) & 1) * 16);

    float accA[2][4][4], accB[2][4][4];
#pragma unroll
    for (int mi = 0; mi < 2; ++mi)
#pragma unroll
        for (int ni = 0; ni < 4; ++ni)
#pragma unroll
            for (int cc = 0; cc < 4; ++cc) { accA[mi][ni][cc] = 0.f; accB[mi][ni][cc] = 0.f; }

    // ---- prefetch chunk 0 ----
    {
        uint32_t stg = sb + OFF_STG;
        size_t koff = (size_t)cch * 16;
        uint32_t d = stg + crow * 80 + cch * 16;
        CP16(d,               pza + (size_t)(i0 + crow) * 512 + koff);
        CP16(d + TILE_B,      pza + (size_t)(j0 + crow) * 512 + koff);
        CP16(d + 2 * TILE_B,  pzb + (size_t)(i0 + crow) * 512 + koff);
        CP16(d + 3 * TILE_B,  pzb + (size_t)(j0 + crow) * 512 + koff);
        CP_COMMIT();
    }

#pragma unroll
    for (int c = 0; c < NCHUNK; ++c) {
        if (c + 1 < NCHUNK) {
            uint32_t stg = sb + OFF_STG + ((c + 1) & 1) * STAGE_B;
            size_t koff = (size_t)(c + 1) * 64 + (size_t)cch * 16;
            uint32_t d = stg + crow * 80 + cch * 16;
            CP16(d,               pza + (size_t)(i0 + crow) * 512 + koff);
            CP16(d + TILE_B,      pza + (size_t)(j0 + crow) * 512 + koff);
            CP16(d + 2 * TILE_B,  pzb + (size_t)(i0 + crow) * 512 + koff);
            CP16(d + 3 * TILE_B,  pzb + (size_t)(j0 + crow) * 512 + koff);
            CP_COMMIT();
            CP_WAIT(1);
        } else {
            CP_WAIT(0);
        }
        __syncthreads();

        uint32_t stg = sb + OFF_STG + (c & 1) * STAGE_B;
        uint32_t tAi = stg, tAj = stg + TILE_B, tBi = stg + 2 * TILE_B, tBj = stg + 3 * TILE_B;
#pragma unroll
        for (int ks = 0; ks < 2; ++ks) {
            uint32_t kb = ks * 32;
            uint32_t aA0[4], aA1[4], bA0[4], bA1[4];
            ldmx4(aA0, tAi + aoff + kb);
            ldmx4(aA1, tAi + aoff + 1280 + kb);
            ldmx4(bA0, tAj + boff + kb);
            ldmx4(bA1, tAj + boff + 1280 + kb);
            mma16816(accA[0][0], aA0, &bA0[0]);
            mma16816(accA[0][1], aA0, &bA0[2]);
            mma16816(accA[0][2], aA0, &bA1[0]);
            mma16816(accA[0][3], aA0, &bA1[2]);
            mma16816(accA[1][0], aA1, &bA0[0]);
            mma16816(accA[1][1], aA1, &bA0[2]);
            mma16816(accA[1][2], aA1, &bA1[0]);
            mma16816(accA[1][3], aA1, &bA1[2]);

            uint32_t aB0[4], aB1[4], bB0[4], bB1[4];
            ldmx4(aB0, tBi + aoff + kb);
            ldmx4(aB1, tBi + aoff + 1280 + kb);
            ldmx4(bB0, tBj + boff + kb);
            ldmx4(bB1, tBj + boff + 1280 + kb);
            mma16816(accB[0][0], aB0, &bB0[0]);
            mma16816(accB[0][1], aB0, &bB0[2]);
            mma16816(accB[0][2], aB0, &bB1[0]);
            mma16816(accB[0][3], aB0, &bB1[2]);
            mma16816(accB[1][0], aB1, &bB0[0]);
            mma16816(accB[1][1], aB1, &bB0[2]);
            mma16816(accB[1][2], aB1, &bB1[0]);
            mma16816(accB[1][3], aB1, &bB1[2]);
        }
        __syncthreads();
    }

    // ---------------- epilogue ----------------
    float xai[4], xbi[4];     // rows: (mi, rr)
#pragma unroll
    for (int mi = 0; mi < 2; ++mi)
#pragma unroll
        for (int rr = 0; rr < 2; ++rr) {
            int r = wr * 32 + 16 * mi + 8 * rr + g;
            xai[2 * mi + rr] = sxai[r];
            xbi[2 * mi + rr] = sxbi[r];
        }
    float xaj[8], xbj[8];     // cols: (ni, jc)
#pragma unroll
    for (int ni = 0; ni < 4; ++ni)
#pragma unroll
        for (int jc = 0; jc < 2; ++jc) {
            int cn = wc * 32 + 8 * ni + 2 * t + jc;
            xaj[2 * ni + jc] = sxaj[cn];
            xbj[2 * ni + jc] = sxbj[cn];
        }

    float rowA[4] = {0, 0, 0, 0}, rowB[4] = {0, 0, 0, 0};
    float colA[8] = {0, 0, 0, 0, 0, 0, 0, 0}, colB[8] = {0, 0, 0, 0, 0, 0, 0, 0};
    float pAB = 0.f, pAA = 0.f, pBB = 0.f, pA = 0.f, pB = 0.f;

#pragma unroll
    for (int mi = 0; mi < 2; ++mi)
#pragma unroll
        for (int ni = 0; ni < 4; ++ni)
#pragma unroll
            for (int cc = 0; cc < 4; ++cc) {
                int rr = cc >> 1, jc = cc & 1;
                float Da = sqrtf(fmaxf(xai[2 * mi + rr] + xaj[2 * ni + jc] - 2.f * accA[mi][ni][cc], 1e-8f));
                float Db = sqrtf(fmaxf(xbi[2 * mi + rr] + xbj[2 * ni + jc] - 2.f * accB[mi][ni][cc], 1e-8f));
                rowA[2 * mi + rr] += Da; rowB[2 * mi + rr] += Db;
                colA[2 * ni + jc] += Da; colB[2 * ni + jc] += Db;
                pAB += Da * Db; pAA += Da * Da; pBB += Db * Db;
                pA += Da; pB += Db;
            }

    // row sums: reduce over t lanes (xor 1,2)
#pragma unroll
    for (int q = 0; q < 4; ++q) {
        rowA[q] += __shfl_xor_sync(0xffffffffu, rowA[q], 1);
        rowA[q] += __shfl_xor_sync(0xffffffffu, rowA[q], 2);
        rowB[q] += __shfl_xor_sync(0xffffffffu, rowB[q], 1);
        rowB[q] += __shfl_xor_sync(0xffffffffu, rowB[q], 2);
    }
    if (t == 0) {
#pragma unroll
        for (int mi = 0; mi < 2; ++mi)
#pragma unroll
            for (int rr = 0; rr < 2; ++rr) {
                int r = i0 + wr * 32 + 16 * mi + 8 * rr + g;
                atomicAdd(&g_rowsum_a[r], (double)rowA[2 * mi + rr]);
                atomicAdd(&g_rowsum_b[r], (double)rowB[2 * mi + rr]);
            }
    }
    // col sums (mirror) only off-diagonal: reduce over g (xor 4,8,16)
    if (!diag) {
#pragma unroll
        for (int q = 0; q < 8; ++q) {
            colA[q] += __shfl_xor_sync(0xffffffffu, colA[q], 4);
            colA[q] += __shfl_xor_sync(0xffffffffu, colA[q], 8);
            colA[q] += __shfl_xor_sync(0xffffffffu, colA[q], 16);
            colB[q] += __shfl_xor_sync(0xffffffffu, colB[q], 4);
            colB[q] += __shfl_xor_sync(0xffffffffu, colB[q], 8);
            colB[q] += __shfl_xor_sync(0xffffffffu, colB[q], 16);
        }
        if (g == 0) {
#pragma unroll
            for (int ni = 0; ni < 4; ++ni)
#pragma unroll
                for (int jc = 0; jc < 2; ++jc) {
                    int cn = j0 + wc * 32 + 8 * ni + 2 * t + jc;
                    atomicAdd(&g_rowsum_a[cn], (double)colA[2 * ni + jc]);
                    atomicAdd(&g_rowsum_b[cn], (double)colB[2 * ni + jc]);
                }
        }
    }
    float w = diag ? 1.f : 2.f;
#pragma unroll
    for (int o = 16; o; o >>= 1) {
        pAB += __shfl_xor_sync(0xffffffffu, pAB, o);
        pAA += __shfl_xor_sync(0xffffffffu, pAA, o);
        pBB += __shfl_xor_sync(0xffffffffu, pBB, o);
        pA  += __shfl_xor_sync(0xffffffffu, pA, o);
        pB  += __shfl_xor_sync(0xffffffffu, pB, o);
    }
    if (lane == 0) {
        atomicAdd(&g_prod[0], (double)(w * pAB));
        atomicAdd(&g_prod[1], (double)(w * pAA));
        atomicAdd(&g_prod[2], (double)(w * pBB));
        atomicAdd(&g_grand[0], (double)(w * pA));
        atomicAdd(&g_grand[1], (double)(w * pB));
    }
}

// ------------------------------- final ---------------------------------------
__global__ void k_final(const float* __restrict__ intra_wsi,
                        const float* __restrict__ intra_ct,
                        float* __restrict__ out) {
    __shared__ double s0[256], s1[256], s2[256];
    double mab = 0.0, maa = 0.0, mbb = 0.0;
    for (int i = threadIdx.x; i < BN; i += 256) {
        double ra = g_rowsum_a[i], rb = g_rowsum_b[i];
        mab += ra * rb; maa += ra * ra; mbb += rb * rb;
    }
    s0[threadIdx.x] = mab; s1[threadIdx.x] = maa; s2[threadIdx.x] = mbb;
    __syncthreads();
    for (int o = 128; o > 0; o >>= 1) {
        if (threadIdx.x < o) {
            s0[threadIdx.x] += s0[threadIdx.x + o];
            s1[threadIdx.x] += s1[threadIdx.x + o];
            s2[threadIdx.x] += s2[threadIdx.x + o];
        }
        __syncthreads();
    }
    if (threadIdx.x == 0) {
        double n = (double)BN, n2 = n * n;
        double Ga = g_grand[0], Gb = g_grand[1];
        double SAB = g_prod[0] - (2.0 / n) * s0[0] + Ga * Gb / n2;
        double SAA = g_prod[1] - (2.0 / n) * s1[0] + Ga * Ga / n2;
        double SBB = g_prod[2] - (2.0 / n) * s2[0] + Gb * Gb / n2;
        double dcov = SAB / n2, va = SAA / n2, vb = SBB / n2;
        double l_cca = 1.0 - dcov / sqrt(fmax(va * vb, 1e-8));
        double l_intra = (double)intra_wsi[0] + (double)intra_ct[0];
        out[0] = (float)(g_cox[0] + g_cox[1] + 0.1 * l_cca + 0.05 * l_intra);
    }
}

// ------------------------------- launch --------------------------------------
extern "C" void kernel_launch(void* const* d_in, const int* in_sizes, int n_in,
                              void* d_out, int out_size) {
    const float* risk_os   = (const float*)d_in[0];
    const float* risk_rfs  = (const float*)d_in[1];
    const float* z_ct      = (const float*)d_in[2];
    const float* z_wsi     = (const float*)d_in[3];
    const float* intra_wsi = (const float*)d_in[4];
    const float* intra_ct  = (const float*)d_in[5];
    const int* evt_os  = (const int*)d_in[6];
    const int* tm_os   = (const int*)d_in[7];
    const int* evt_rfs = (const int*)d_in[8];
    const int* tm_rfs  = (const int*)d_in[9];
    float* out = (float*)d_out;

    cudaFuncSetAttribute(k_dist, cudaFuncAttributeMaxDynamicSharedMemorySize, SMEM_TOTAL);

    k_zero<<<32, 256>>>();
    k_max<<<2, 256>>>(risk_os, risk_rfs);
    k_bucket<<<dim3(32, 2), 256>>>(risk_os, evt_os, tm_os, risk_rfs, evt_rfs, tm_rfs);
    k_cox<<<1, 32>>>();
    k_cvt<<<BN / 8, 256>>>(z_ct, z_wsi);
    k_dist<<<dim3(BN / TS, BN / TS), 512, SMEM_TOTAL>>>();
    k_final<<<1, 256>>>(intra_wsi, intra_ct, out);
}